// round 13
// baseline (speedup 1.0000x reference)
#include <cuda_runtime.h>
#include <cuda_fp16.h>
#include <cstdint>

#define NPTS   2048
#define NBATCH 8
#define NSAMP  64
#define R2     0.36f

// 4 MB fp16 feature table: f[b][m][c], c = 0..127
__device__ __half g_feat_h[NBATCH * NPTS * 128];

__device__ __forceinline__ uint32_t relu_pack_h2f(float lo, float hi) {
    union { __half2 h; uint32_t u; } cv;
    cv.h = __floats2half2_rn(fmaxf(lo, 0.f), fmaxf(hi, 0.f));
    return cv.u;
}

// W2 transposed in smem, pad-132 rows (528 B, 16B-aligned): [o][c] = W2[c][o]
#define W2T_STRIDE 132

// ---------------------------------------------------------------------------
// Kernel 1: f[b,m,:] = relu(W2*relu(W1*x+b1)+b2), fp16 output.
// Scalar fp32 math (FFMA2 variants measured consistently slower). Warp =
// 32 points (lanes) x one 32-channel quarter; acc[32] fp32. h1 computed in
// two 32-wide chunks to bound live registers. W2 transpose preamble reads
// coalesced (o fast axis); broadcast LDS.128 feeds 4 channels per load.
// ---------------------------------------------------------------------------
__global__ __launch_bounds__(256, 2) void feat_kernel(
    const float* __restrict__ x, const float* __restrict__ W1,
    const float* __restrict__ b1, const float* __restrict__ W2,
    const float* __restrict__ b2)
{
    __shared__ float sW1[64 * 3];
    __shared__ float sb1[64];
    __shared__ float sb2[128];
    __shared__ float sW2t[64 * W2T_STRIDE];   // ~33.8 KB

    const int tid = threadIdx.x;
    for (int i = tid; i < 192; i += 256) sW1[i] = W1[i];
    for (int i = tid; i < 64;  i += 256) sb1[i] = b1[i];
    for (int i = tid; i < 128; i += 256) sb2[i] = b2[i];
#pragma unroll
    for (int k = 0; k < 32; k++) {            // 8192 = 32 * 256
        const int i = k * 256 + tid;
        const int o = i & 63;                 // fast axis -> coalesced read
        const int c = i >> 6;
        sW2t[o * W2T_STRIDE + c] = W2[c * 64 + o];
    }
    __syncthreads();

    const int lane    = tid & 31;
    const int gwarp   = blockIdx.x * 8 + (tid >> 5);  // 0..2047
    const int quarter = gwarp & 3;
    const int cbase   = quarter * 32;
    const int p       = (gwarp >> 2) * 32 + lane;     // 0..16383

    const float x0 = x[p * 3 + 0];
    const float x1 = x[p * 3 + 1];
    const float x2 = x[p * 3 + 2];

    float acc[32];
#pragma unroll
    for (int k = 0; k < 32; k++) acc[k] = sb2[cbase + k];

#pragma unroll 1
    for (int och = 0; och < 2; och++) {
        const int obase = och * 32;
        float h1[32];
#pragma unroll
        for (int oo = 0; oo < 32; oo++) {
            const int o = obase + oo;
            float v = sb1[o];
            v = fmaf(sW1[o * 3 + 0], x0, v);
            v = fmaf(sW1[o * 3 + 1], x1, v);
            v = fmaf(sW1[o * 3 + 2], x2, v);
            h1[oo] = fmaxf(v, 0.0f);
        }
#pragma unroll 1
        for (int oo = 0; oo < 32; oo++) {
            const float hv = h1[oo];
            const float4* wrow = reinterpret_cast<const float4*>(
                sW2t + (obase + oo) * W2T_STRIDE + cbase);
#pragma unroll
            for (int j = 0; j < 8; j++) {
                const float4 w = wrow[j];   // LDS.128, warp-broadcast
                acc[4 * j + 0] = fmaf(w.x, hv, acc[4 * j + 0]);
                acc[4 * j + 1] = fmaf(w.y, hv, acc[4 * j + 1]);
                acc[4 * j + 2] = fmaf(w.z, hv, acc[4 * j + 2]);
                acc[4 * j + 3] = fmaf(w.w, hv, acc[4 * j + 3]);
            }
        }
    }

    // relu -> fp16: word k = half2(channels cbase+2k, cbase+2k+1)
    __half* dst = g_feat_h + (size_t)p * 128 + cbase;
#pragma unroll
    for (int g = 0; g < 4; g++) {
        uint4 wv;
        wv.x = relu_pack_h2f(acc[8 * g + 0], acc[8 * g + 1]);
        wv.y = relu_pack_h2f(acc[8 * g + 2], acc[8 * g + 3]);
        wv.z = relu_pack_h2f(acc[8 * g + 4], acc[8 * g + 5]);
        wv.w = relu_pack_h2f(acc[8 * g + 6], acc[8 * g + 7]);
        reinterpret_cast<uint4*>(dst)[g] = wv;
    }
}

// ---------------------------------------------------------------------------
// Kernel 2: fused ball-query + fp16 feature max-pool.
// 64 queries per block (warp handles 2 sequentially) -> 256 blocks =
// SINGLE wave (vs 1.73 before) and the 32 KB sx preamble amortized 2x.
// Phase A: ballot + prefix-popc first-64-accepted list (reference order).
// Phase B: half-warps gather 2 fp16 rows per step (4 LDG.128 in flight).
// ---------------------------------------------------------------------------
__global__ __launch_bounds__(1024, 2) void group_kernel(
    const float* __restrict__ x, float* __restrict__ out)
{
    __shared__ float4   sx[NPTS];          // 32 KB
    __shared__ float    sout[64 * 133];    // 34 KB (133: conflict-free rdbk)
    __shared__ uint16_t slist[32][NSAMP];  // 4 KB

    const int b   = blockIdx.y;
    const int n0  = blockIdx.x * 64;
    const int tid = threadIdx.x;
    const float* xb = x + (size_t)b * NPTS * 3;

    for (int p = tid; p < NPTS; p += 1024) {
        const float px = xb[p * 3 + 0];
        const float py = xb[p * 3 + 1];
        const float pz = xb[p * 3 + 2];
        sx[p] = make_float4(px, py, pz, px * px + py * py + pz * pz);
    }
    __syncthreads();

    const int w    = tid >> 5;
    const int lane = tid & 31;
    const unsigned lt_mask = (1u << lane) - 1u;
    const int half = lane >> 4;
    const int lc   = lane & 15;
    const uint4* fb = reinterpret_cast<const uint4*>(
        g_feat_h + (size_t)b * NPTS * 128);

#pragma unroll 1
    for (int qi = 0; qi < 2; qi++) {
        const int n = n0 + qi * 32 + w;
        const float4 q = sx[n];

        // Phase A: first-64-accepted index list (ascending m)
        int count = 0;
        for (int base = 0; base < NPTS; base += 32) {
            const float4 pm = sx[base + lane];
            const float dist = q.w + pm.w -
                2.0f * (q.x * pm.x + q.y * pm.y + q.z * pm.z);
            const unsigned mask = __ballot_sync(0xffffffffu, !(dist > R2));
            const int take = min(__popc(mask), NSAMP - count);
            if ((mask >> lane) & 1u) {
                const int pos = count + __popc(mask & lt_mask);
                if (pos < count + take) slist[w][pos] = (uint16_t)(base + lane);
            }
            count += take;
            if (count >= NSAMP) break;
        }
        __syncwarp();

        // Phase B: half-warps gather 2 rows per LDG.128 step
        __half2 a0 = __float2half2_rn(0.f), a1 = a0, a2 = a0, a3 = a0;
        if (count == NSAMP) {
#pragma unroll
            for (int i = 0; i < NSAMP; i += 8) {
                const int m0 = slist[w][i + 0 + half];
                const int m1 = slist[w][i + 2 + half];
                const int m2 = slist[w][i + 4 + half];
                const int m3 = slist[w][i + 6 + half];
                const uint4 v0 = fb[m0 * 16 + lc];
                const uint4 v1 = fb[m1 * 16 + lc];
                const uint4 v2 = fb[m2 * 16 + lc];
                const uint4 v3 = fb[m3 * 16 + lc];
                a0 = __hmax2(a0, *reinterpret_cast<const __half2*>(&v0.x));
                a1 = __hmax2(a1, *reinterpret_cast<const __half2*>(&v0.y));
                a2 = __hmax2(a2, *reinterpret_cast<const __half2*>(&v0.z));
                a3 = __hmax2(a3, *reinterpret_cast<const __half2*>(&v0.w));
                a0 = __hmax2(a0, *reinterpret_cast<const __half2*>(&v1.x));
                a1 = __hmax2(a1, *reinterpret_cast<const __half2*>(&v1.y));
                a2 = __hmax2(a2, *reinterpret_cast<const __half2*>(&v1.z));
                a3 = __hmax2(a3, *reinterpret_cast<const __half2*>(&v1.w));
                a0 = __hmax2(a0, *reinterpret_cast<const __half2*>(&v2.x));
                a1 = __hmax2(a1, *reinterpret_cast<const __half2*>(&v2.y));
                a2 = __hmax2(a2, *reinterpret_cast<const __half2*>(&v2.z));
                a3 = __hmax2(a3, *reinterpret_cast<const __half2*>(&v2.w));
                a0 = __hmax2(a0, *reinterpret_cast<const __half2*>(&v3.x));
                a1 = __hmax2(a1, *reinterpret_cast<const __half2*>(&v3.y));
                a2 = __hmax2(a2, *reinterpret_cast<const __half2*>(&v3.z));
                a3 = __hmax2(a3, *reinterpret_cast<const __half2*>(&v3.w));
            }
        } else {
            for (int i = 0; i < count; i += 4) {
                const int l0 = i + half;
                const int l1 = i + 2 + half;
                const int m0 = slist[w][l0 < count ? l0 : 0];
                const int m1 = slist[w][l1 < count ? l1 : 0];
                const uint4 v0 = fb[m0 * 16 + lc];
                const uint4 v1 = fb[m1 * 16 + lc];
                a0 = __hmax2(a0, *reinterpret_cast<const __half2*>(&v0.x));
                a1 = __hmax2(a1, *reinterpret_cast<const __half2*>(&v0.y));
                a2 = __hmax2(a2, *reinterpret_cast<const __half2*>(&v0.z));
                a3 = __hmax2(a3, *reinterpret_cast<const __half2*>(&v0.w));
                a0 = __hmax2(a0, *reinterpret_cast<const __half2*>(&v1.x));
                a1 = __hmax2(a1, *reinterpret_cast<const __half2*>(&v1.y));
                a2 = __hmax2(a2, *reinterpret_cast<const __half2*>(&v1.z));
                a3 = __hmax2(a3, *reinterpret_cast<const __half2*>(&v1.w));
            }
        }

        // combine the two half-warps
        {
            uint32_t u;
            u = __shfl_xor_sync(0xffffffffu, *reinterpret_cast<uint32_t*>(&a0), 16);
            a0 = __hmax2(a0, *reinterpret_cast<__half2*>(&u));
            u = __shfl_xor_sync(0xffffffffu, *reinterpret_cast<uint32_t*>(&a1), 16);
            a1 = __hmax2(a1, *reinterpret_cast<__half2*>(&u));
            u = __shfl_xor_sync(0xffffffffu, *reinterpret_cast<uint32_t*>(&a2), 16);
            a2 = __hmax2(a2, *reinterpret_cast<__half2*>(&u));
            u = __shfl_xor_sync(0xffffffffu, *reinterpret_cast<uint32_t*>(&a3), 16);
            a3 = __hmax2(a3, *reinterpret_cast<__half2*>(&u));
        }

        // stage sout[qi*32+w][c]: lane lc holds channels 8*lc..8*lc+7
        {
            float* so = sout + (qi * 32 + w) * 133 + 8 * lc;
            if (half == 0) {
                const float2 f0 = __half22float2(a0);
                const float2 f1 = __half22float2(a1);
                so[0] = f0.x; so[1] = f0.y; so[2] = f1.x; so[3] = f1.y;
            } else {
                const float2 f2 = __half22float2(a2);
                const float2 f3 = __half22float2(a3);
                so[4] = f2.x; so[5] = f2.y; so[6] = f3.x; so[7] = f3.y;
            }
        }
        __syncwarp();
    }
    __syncthreads();

    // out[b, c, n0+qq]: 64 consecutive n per c-row; warp spans 32 n -> 128 B
    float* ob = out + (size_t)b * 128 * NPTS + n0;
    const int qq = tid & 63;
    const int cr = tid >> 6;          // 0..15
#pragma unroll
    for (int pass = 0; pass < 8; pass++) {
        const int c = pass * 16 + cr;
        ob[(size_t)c * NPTS + qq] = sout[qq * 133 + c];
    }
}

extern "C" void kernel_launch(void* const* d_in, const int* in_sizes, int n_in,
                              void* d_out, int out_size)
{
    const float* x  = (const float*)d_in[0];   // (8, 2048, 3)
    const float* W1 = (const float*)d_in[1];   // (64, 3)
    const float* b1 = (const float*)d_in[2];   // (64,)
    const float* W2 = (const float*)d_in[3];   // (128, 64)
    const float* b2 = (const float*)d_in[4];   // (128,)
    float* out = (float*)d_out;                // (8, 128, 2048)

    feat_kernel<<<256, 256>>>(x, W1, b1, W2, b2);
    group_kernel<<<dim3(32, 8), 1024>>>(x, out);
}

// round 14
// speedup vs baseline: 1.3801x; 1.3801x over previous
#include <cuda_runtime.h>
#include <cuda_fp16.h>
#include <cstdint>

#define NPTS   2048
#define NBATCH 8
#define NSAMP  64
#define R2     0.36f

// 4 MB fp16 feature table: f[b][m][c], c = 0..127
__device__ __half g_feat_h[NBATCH * NPTS * 128];

__device__ __forceinline__ uint32_t relu_pack_h2f(float lo, float hi) {
    union { __half2 h; uint32_t u; } cv;
    cv.h = __floats2half2_rn(fmaxf(lo, 0.f), fmaxf(hi, 0.f));
    return cv.u;
}

__device__ __forceinline__ void ldsm_x4(uint32_t& r0, uint32_t& r1,
                                        uint32_t& r2, uint32_t& r3,
                                        uint32_t addr) {
    asm volatile("ldmatrix.sync.aligned.m8n8.x4.shared.b16 {%0,%1,%2,%3}, [%4];"
                 : "=r"(r0), "=r"(r1), "=r"(r2), "=r"(r3) : "r"(addr));
}
__device__ __forceinline__ void ldsm_x2_t(uint32_t& r0, uint32_t& r1,
                                          uint32_t addr) {
    asm volatile("ldmatrix.sync.aligned.m8n8.x2.trans.shared.b16 {%0,%1}, [%2];"
                 : "=r"(r0), "=r"(r1) : "r"(addr));
}
__device__ __forceinline__ void mma16816(float* c, const uint32_t* a,
                                         const uint32_t* b) {
    asm volatile(
        "mma.sync.aligned.m16n8k16.row.col.f32.f16.f16.f32 "
        "{%0,%1,%2,%3}, {%4,%5,%6,%7}, {%8,%9}, {%0,%1,%2,%3};"
        : "+f"(c[0]), "+f"(c[1]), "+f"(c[2]), "+f"(c[3])
        : "r"(a[0]), "r"(a[1]), "r"(a[2]), "r"(a[3]), "r"(b[0]), "r"(b[1]));
}

// padded smem strides (halfs): rows shift by 4 banks -> ldmatrix conflict-free
#define SH1_STRIDE 72    // 144 B/row, 16B-aligned
#define WT_STRIDE  136   // 272 B/row, 16B-aligned

// ---------------------------------------------------------------------------
// Kernel 1 (HMMA): f[b,m,:] = relu(W2*relu(W1*x+b1)+b2), fp16 output.
// Block = 128 points, 128 threads (4 warps). Phase 1: each thread computes
// h1[64] fp32 for its point, rounds to fp16 into padded smem. Phase 2: each
// warp does a 32x128x64 GEMM via mma.m16n8k16 (fp32 accumulate): A = h1
// (ldmatrix.x4, row-major), B = W2^T (ldmatrix.x2.trans, k-major), bias +
// relu + fp16-pack epilogue straight from C fragments.
// ---------------------------------------------------------------------------
__global__ __launch_bounds__(128, 4) void feat_kernel(
    const float* __restrict__ x, const float* __restrict__ W1,
    const float* __restrict__ b1, const float* __restrict__ W2,
    const float* __restrict__ b2)
{
    __shared__ float  sW1[192];
    __shared__ float  sb1[64];
    __shared__ float  sb2[128];
    __shared__ __half sh1[128 * SH1_STRIDE];   // 18.4 KB
    __shared__ __half sWt[64 * WT_STRIDE];     // 17.4 KB, [o][c] = W2[c][o]

    const int tid = threadIdx.x;
    for (int i = tid; i < 192; i += 128) sW1[i] = W1[i];
    for (int i = tid; i < 64;  i += 128) sb1[i] = b1[i];
    for (int i = tid; i < 128; i += 128) sb2[i] = b2[i];
#pragma unroll
    for (int k = 0; k < 64; k++) {            // 8192 = 64 * 128
        const int i = k * 128 + tid;
        const int o = i & 63;                 // fast axis -> coalesced read
        const int c = i >> 6;
        sWt[o * WT_STRIDE + c] = __float2half(W2[c * 64 + o]);
    }
    __syncthreads();

    // Phase 1: h1 for point p = blockIdx.x*128 + tid
    {
        const int p = blockIdx.x * 128 + tid;
        const float x0 = x[p * 3 + 0];
        const float x1 = x[p * 3 + 1];
        const float x2 = x[p * 3 + 2];
#pragma unroll
        for (int og = 0; og < 8; og++) {
            uint32_t wds[4];
#pragma unroll
            for (int j = 0; j < 4; j++) {
                const int o = og * 8 + j * 2;
                float v0 = sb1[o], v1 = sb1[o + 1];
                v0 = fmaf(sW1[o * 3 + 0], x0, v0);
                v0 = fmaf(sW1[o * 3 + 1], x1, v0);
                v0 = fmaf(sW1[o * 3 + 2], x2, v0);
                v1 = fmaf(sW1[o * 3 + 3], x0, v1);
                v1 = fmaf(sW1[o * 3 + 4], x1, v1);
                v1 = fmaf(sW1[o * 3 + 5], x2, v1);
                wds[j] = relu_pack_h2f(v0, v1);
            }
            *reinterpret_cast<uint4*>(&sh1[tid * SH1_STRIDE + og * 8]) =
                make_uint4(wds[0], wds[1], wds[2], wds[3]);
        }
    }
    __syncthreads();

    // Phase 2: per-warp 32x128x64 GEMM
    const int lane = tid & 31;
    const int warp = tid >> 5;
    const uint32_t sh1_b = (uint32_t)__cvta_generic_to_shared(sh1);
    const uint32_t wt_b  = (uint32_t)__cvta_generic_to_shared(sWt);

    uint32_t afrag[2][4][4];   // [mtile][kstep][4]
#pragma unroll
    for (int mt = 0; mt < 2; mt++)
#pragma unroll
        for (int ks = 0; ks < 4; ks++) {
            const uint32_t addr = sh1_b +
                ((warp * 32 + mt * 16 + (lane & 15)) * SH1_STRIDE +
                 ks * 16 + (lane >> 4) * 8) * 2;
            ldsm_x4(afrag[mt][ks][0], afrag[mt][ks][1],
                    afrag[mt][ks][2], afrag[mt][ks][3], addr);
        }

    const int pbase = blockIdx.x * 128 + warp * 32;
#pragma unroll 1
    for (int chunk = 0; chunk < 4; chunk++) {
        uint32_t bfrag[4][4][2];   // [ntile][kstep][2]
#pragma unroll
        for (int nt = 0; nt < 4; nt++)
#pragma unroll
            for (int ks = 0; ks < 4; ks++) {
                const uint32_t addr = wt_b +
                    ((ks * 16 + (lane & 15)) * WT_STRIDE +
                     chunk * 32 + nt * 8) * 2;
                ldsm_x2_t(bfrag[nt][ks][0], bfrag[nt][ks][1], addr);
            }

        float c[2][4][4];
#pragma unroll
        for (int mt = 0; mt < 2; mt++)
#pragma unroll
            for (int nt = 0; nt < 4; nt++)
#pragma unroll
                for (int v = 0; v < 4; v++) c[mt][nt][v] = 0.0f;

#pragma unroll
        for (int ks = 0; ks < 4; ks++)
#pragma unroll
            for (int mt = 0; mt < 2; mt++)
#pragma unroll
                for (int nt = 0; nt < 4; nt++)
                    mma16816(c[mt][nt], afrag[mt][ks], bfrag[nt][ks]);

        // epilogue: bias + relu + fp16 pack; C frag: lane holds rows
        // (lane>>2, +8), cols 2*(lane&3)+{0,1} of each 16x8 tile
#pragma unroll
        for (int mt = 0; mt < 2; mt++)
#pragma unroll
            for (int nt = 0; nt < 4; nt++) {
                const int chn = chunk * 32 + nt * 8 + 2 * (lane & 3);
                const float2 bias =
                    *reinterpret_cast<const float2*>(&sb2[chn]);
                const int r0 = pbase + mt * 16 + (lane >> 2);
                *reinterpret_cast<uint32_t*>(
                    &g_feat_h[(size_t)r0 * 128 + chn]) =
                    relu_pack_h2f(c[mt][nt][0] + bias.x,
                                  c[mt][nt][1] + bias.y);
                *reinterpret_cast<uint32_t*>(
                    &g_feat_h[(size_t)(r0 + 8) * 128 + chn]) =
                    relu_pack_h2f(c[mt][nt][2] + bias.x,
                                  c[mt][nt][3] + bias.y);
            }
    }
}

// ---------------------------------------------------------------------------
// Kernel 2: fused ball-query + fp16 feature max-pool. (R11 exact: best
// measured 23.5us. 32 queries/block, 512 blocks.)
// ---------------------------------------------------------------------------
__global__ __launch_bounds__(1024, 2) void group_kernel(
    const float* __restrict__ x, float* __restrict__ out)
{
    __shared__ float4   sx[NPTS];          // 32 KB
    __shared__ float    sout[32 * 133];    // 17 KB (conflict-free readback)
    __shared__ uint16_t slist[32][NSAMP];  // 4 KB

    const int b   = blockIdx.y;
    const int n0  = blockIdx.x * 32;
    const int tid = threadIdx.x;
    const float* xb = x + (size_t)b * NPTS * 3;

    for (int p = tid; p < NPTS; p += 1024) {
        const float px = xb[p * 3 + 0];
        const float py = xb[p * 3 + 1];
        const float pz = xb[p * 3 + 2];
        sx[p] = make_float4(px, py, pz, px * px + py * py + pz * pz);
    }
    __syncthreads();

    const int w    = tid >> 5;
    const int lane = tid & 31;
    const float4 q = sx[n0 + w];
    const unsigned lt_mask = (1u << lane) - 1u;

    // Phase A: first-64-accepted index list (ascending m, reference order)
    int count = 0;
    for (int base = 0; base < NPTS; base += 32) {
        const float4 pm = sx[base + lane];
        const float dist = q.w + pm.w -
            2.0f * (q.x * pm.x + q.y * pm.y + q.z * pm.z);
        const unsigned mask = __ballot_sync(0xffffffffu, !(dist > R2));
        const int take = min(__popc(mask), NSAMP - count);
        if ((mask >> lane) & 1u) {
            const int pos = count + __popc(mask & lt_mask);
            if (pos < count + take) slist[w][pos] = (uint16_t)(base + lane);
        }
        count += take;
        if (count >= NSAMP) break;
    }
    __syncwarp();

    // Phase B: half-warps gather 2 rows per LDG.128 step
    const int half = lane >> 4;
    const int lc   = lane & 15;
    const uint4* fb = reinterpret_cast<const uint4*>(
        g_feat_h + (size_t)b * NPTS * 128);
    __half2 a0 = __float2half2_rn(0.f), a1 = a0, a2 = a0, a3 = a0;

    if (count == NSAMP) {
#pragma unroll
        for (int i = 0; i < NSAMP; i += 8) {
            const int m0 = slist[w][i + 0 + half];
            const int m1 = slist[w][i + 2 + half];
            const int m2 = slist[w][i + 4 + half];
            const int m3 = slist[w][i + 6 + half];
            const uint4 v0 = fb[m0 * 16 + lc];
            const uint4 v1 = fb[m1 * 16 + lc];
            const uint4 v2 = fb[m2 * 16 + lc];
            const uint4 v3 = fb[m3 * 16 + lc];
            a0 = __hmax2(a0, *reinterpret_cast<const __half2*>(&v0.x));
            a1 = __hmax2(a1, *reinterpret_cast<const __half2*>(&v0.y));
            a2 = __hmax2(a2, *reinterpret_cast<const __half2*>(&v0.z));
            a3 = __hmax2(a3, *reinterpret_cast<const __half2*>(&v0.w));
            a0 = __hmax2(a0, *reinterpret_cast<const __half2*>(&v1.x));
            a1 = __hmax2(a1, *reinterpret_cast<const __half2*>(&v1.y));
            a2 = __hmax2(a2, *reinterpret_cast<const __half2*>(&v1.z));
            a3 = __hmax2(a3, *reinterpret_cast<const __half2*>(&v1.w));
            a0 = __hmax2(a0, *reinterpret_cast<const __half2*>(&v2.x));
            a1 = __hmax2(a1, *reinterpret_cast<const __half2*>(&v2.y));
            a2 = __hmax2(a2, *reinterpret_cast<const __half2*>(&v2.z));
            a3 = __hmax2(a3, *reinterpret_cast<const __half2*>(&v2.w));
            a0 = __hmax2(a0, *reinterpret_cast<const __half2*>(&v3.x));
            a1 = __hmax2(a1, *reinterpret_cast<const __half2*>(&v3.y));
            a2 = __hmax2(a2, *reinterpret_cast<const __half2*>(&v3.z));
            a3 = __hmax2(a3, *reinterpret_cast<const __half2*>(&v3.w));
        }
    } else {
        for (int i = 0; i < count; i += 4) {
            const int l0 = i + half;
            const int l1 = i + 2 + half;
            const int m0 = slist[w][l0 < count ? l0 : 0];
            const int m1 = slist[w][l1 < count ? l1 : 0];
            const uint4 v0 = fb[m0 * 16 + lc];
            const uint4 v1 = fb[m1 * 16 + lc];
            a0 = __hmax2(a0, *reinterpret_cast<const __half2*>(&v0.x));
            a1 = __hmax2(a1, *reinterpret_cast<const __half2*>(&v0.y));
            a2 = __hmax2(a2, *reinterpret_cast<const __half2*>(&v0.z));
            a3 = __hmax2(a3, *reinterpret_cast<const __half2*>(&v0.w));
            a0 = __hmax2(a0, *reinterpret_cast<const __half2*>(&v1.x));
            a1 = __hmax2(a1, *reinterpret_cast<const __half2*>(&v1.y));
            a2 = __hmax2(a2, *reinterpret_cast<const __half2*>(&v1.z));
            a3 = __hmax2(a3, *reinterpret_cast<const __half2*>(&v1.w));
        }
    }

    // combine the two half-warps
    {
        uint32_t u;
        u = __shfl_xor_sync(0xffffffffu, *reinterpret_cast<uint32_t*>(&a0), 16);
        a0 = __hmax2(a0, *reinterpret_cast<__half2*>(&u));
        u = __shfl_xor_sync(0xffffffffu, *reinterpret_cast<uint32_t*>(&a1), 16);
        a1 = __hmax2(a1, *reinterpret_cast<__half2*>(&u));
        u = __shfl_xor_sync(0xffffffffu, *reinterpret_cast<uint32_t*>(&a2), 16);
        a2 = __hmax2(a2, *reinterpret_cast<__half2*>(&u));
        u = __shfl_xor_sync(0xffffffffu, *reinterpret_cast<uint32_t*>(&a3), 16);
        a3 = __hmax2(a3, *reinterpret_cast<__half2*>(&u));
    }

    // stage sout[q][c]: lane lc holds channels 8*lc..8*lc+7; halves write
    // disjoint 4-channel parts
    {
        float* so = sout + w * 133 + 8 * lc;
        if (half == 0) {
            const float2 f0 = __half22float2(a0);
            const float2 f1 = __half22float2(a1);
            so[0] = f0.x; so[1] = f0.y; so[2] = f1.x; so[3] = f1.y;
        } else {
            const float2 f2 = __half22float2(a2);
            const float2 f3 = __half22float2(a3);
            so[4] = f2.x; so[5] = f2.y; so[6] = f3.x; so[7] = f3.y;
        }
    }
    __syncthreads();

    // out[b, c, n0+qq]: 32 consecutive n per store -> 128 B coalesced
    float* ob = out + (size_t)b * 128 * NPTS + n0;
    const int qq = tid & 31;
    const int c0 = tid >> 5;
#pragma unroll
    for (int pass = 0; pass < 4; pass++) {
        const int c = pass * 32 + c0;
        ob[(size_t)c * NPTS + qq] = sout[qq * 133 + c];
    }
}

extern "C" void kernel_launch(void* const* d_in, const int* in_sizes, int n_in,
                              void* d_out, int out_size)
{
    const float* x  = (const float*)d_in[0];   // (8, 2048, 3)
    const float* W1 = (const float*)d_in[1];   // (64, 3)
    const float* b1 = (const float*)d_in[2];   // (64,)
    const float* W2 = (const float*)d_in[3];   // (128, 64)
    const float* b2 = (const float*)d_in[4];   // (128,)
    float* out = (float*)d_out;                // (8, 128, 2048)

    feat_kernel<<<128, 128>>>(x, W1, b1, W2, b2);
    group_kernel<<<dim3(64, 8), 1024>>>(x, out);
}